// round 13
// baseline (speedup 1.0000x reference)
#include <cuda_runtime.h>
#include <cstdint>

#define HH 512
#define WW 512
#define BB 4
#define NCH 31          // IN_C + DEPTH
#define HW (HH * WW)

// Scratch: feats tensor [B][31][H][W]  (130 MB device global; written before read)
__device__ float g_feats[(size_t)BB * NCH * HW];

// ---------------------------------------------------------------------------
// Init: feats[:,0] = x * sin_w + sin_b   (float4 vectorized)
// ---------------------------------------------------------------------------
__global__ void k_init(const float* __restrict__ x,
                       const float* __restrict__ sin_w,
                       const float* __restrict__ sin_b) {
    int idx = blockIdx.x * blockDim.x + threadIdx.x;   // 0 .. BB*HW/4-1
    float w = sin_w[0], b = sin_b[0];
    int bb = idx >> 16;            // HW/4 = 65536
    int p  = idx & 65535;
    float4 v = reinterpret_cast<const float4*>(x)[idx];
    float4 r = make_float4(fmaf(v.x, w, b), fmaf(v.y, w, b),
                           fmaf(v.z, w, b), fmaf(v.w, w, b));
    reinterpret_cast<float4*>(g_feats)[(size_t)(bb * NCH) * (HW / 4) + p] = r;
}

// ---------------------------------------------------------------------------
// Depth kernel (depths 0..28) — exact R2 champion.
// Block: 256 threads, output tile 64x64; thread = 1 column x 16 rows.
// Staging: 88-float-wide aligned window via 16B cp.async (zfill padding),
// double-buffered across channels.
// ---------------------------------------------------------------------------
template<int D>
__global__ void __launch_bounds__(256)
k_depth(const float* __restrict__ Wmsd,
        const float* __restrict__ bias,
        int di) {
    constexpr int TILE = 64;
    constexpr int RPT  = 16;
    constexpr int TW   = 88;
    constexpr int TH   = TILE + 2 * D;
    constexpr int SBUF = TH * TW;
    constexpr int NV4  = TH * (TW / 4);

    extern __shared__ float sbuf[];

    const int nin = di + 1;
    const int tid = threadIdx.x;
    const int lx  = tid & 63;
    const int grp = tid >> 6;
    const int bx  = blockIdx.x & 7;
    const int by  = blockIdx.x >> 3;
    const int b   = blockIdx.y;
    const int x0  = bx * TILE, y0 = by * TILE;

    const float* fbase = g_feats + (size_t)b * NCH * HW;
    const int oy0 = grp * RPT;
    const int sx  = lx + 12;

    float acc[RPT];
    float bi = __ldg(bias + di);
#pragma unroll
    for (int k = 0; k < RPT; k++) acc[k] = bi;

    auto stage = [&](int c, int sel) {
        const float* plane = fbase + (size_t)c * HW;
        float* dst = sbuf + sel * SBUF;
        for (int idx = tid; idx < NV4; idx += 256) {
            int sy_ = idx / (TW / 4);
            int c4  = idx - sy_ * (TW / 4);
            int gy  = y0 - D + sy_;
            int gx  = x0 - 12 + c4 * 4;
            // 16B chunks are 4-float aligned and W is a multiple of 4, so a
            // chunk is either fully inside the row or fully outside -> zfill.
            bool ok = ((unsigned)gy < HH) && ((unsigned)gx < WW);
            const float* src = ok ? (plane + gy * WW + gx) : plane;
            unsigned sa = (unsigned)__cvta_generic_to_shared(dst + sy_ * TW + c4 * 4);
            int sz = ok ? 16 : 0;
            asm volatile("cp.async.cg.shared.global [%0], [%1], 16, %2;\n"
                         :: "r"(sa), "l"(src), "r"(sz));
        }
        asm volatile("cp.async.commit_group;\n" ::: "memory");
    };

    stage(0, 0);
    asm volatile("cp.async.wait_group 0;\n" ::: "memory");
    __syncthreads();

    int cur = 0;
    for (int c = 0; c < nin; c++) {
        if (c + 1 < nin) stage(c + 1, cur ^ 1);

        const float* wp = Wmsd + ((size_t)di * 30 + c) * 9;
        float w0 = __ldg(wp + 0), w1 = __ldg(wp + 1), w2 = __ldg(wp + 2);
        float w3 = __ldg(wp + 3), w4 = __ldg(wp + 4), w5 = __ldg(wp + 5);
        float w6 = __ldg(wp + 6), w7 = __ldg(wp + 7), w8 = __ldg(wp + 8);

        const float* sb_ = sbuf + cur * SBUF;
#pragma unroll
        for (int rr = 0; rr < RPT + 2 * D; rr++) {
            const float* rp = sb_ + (oy0 + rr) * TW + sx;
            float v0 = rp[-D], v1 = rp[0], v2 = rp[D];
            // input row rr-D feeds out rows rr (w-row0), rr-D (w-row1),
            // rr-2D (w-row2)
            if (rr < RPT)
                acc[rr]       = fmaf(w0, v0, fmaf(w1, v1, fmaf(w2, v2, acc[rr])));
            if (rr >= D && rr < RPT + D)
                acc[rr - D]   = fmaf(w3, v0, fmaf(w4, v1, fmaf(w5, v2, acc[rr - D])));
            if (rr >= 2 * D)
                acc[rr - 2*D] = fmaf(w6, v0, fmaf(w7, v1, fmaf(w8, v2, acc[rr - 2*D])));
        }

        if (c + 1 < nin)
            asm volatile("cp.async.wait_group 0;\n" ::: "memory");
        __syncthreads();
        cur ^= 1;
    }

    float* op = g_feats + (size_t)b * NCH * HW + (size_t)nin * HW
              + (size_t)(y0 + oy0) * WW + (x0 + lx);
#pragma unroll
    for (int k = 0; k < RPT; k++)
        op[(size_t)k * WW] = fmaxf(acc[k], 0.0f);
}

// ---------------------------------------------------------------------------
// LAST depth kernel (depth 29, D=10, nin=30) with the final 1x1 conv fused:
// while each channel tile c is staged in smem, accumulate
//   yacc[k] += convW[c] * feats_c(pixel)            (16 LDS+FMA per phase)
// from the already-staged data. After the conv loop, h29 is in registers:
//   yacc[k] += convW[30] * relu(h29);  out = yacc*sw + sb  -> write d_out.
// h29 is never stored; k_final is eliminated entirely (saves a full 130MB
// read pass + 4MB write).
// ---------------------------------------------------------------------------
__global__ void __launch_bounds__(256)
k_depth_last(const float* __restrict__ Wmsd,
             const float* __restrict__ bias,
             const float* __restrict__ convW,
             const float* __restrict__ convB,
             const float* __restrict__ sout_w,
             const float* __restrict__ sout_b,
             float* __restrict__ out) {
    constexpr int D    = 10;
    constexpr int DI   = 29;
    constexpr int TILE = 64;
    constexpr int RPT  = 16;
    constexpr int TW   = 88;
    constexpr int TH   = TILE + 2 * D;
    constexpr int SBUF = TH * TW;
    constexpr int NV4  = TH * (TW / 4);

    extern __shared__ float sbuf[];

    const int nin = DI + 1;               // 30
    const int tid = threadIdx.x;
    const int lx  = tid & 63;
    const int grp = tid >> 6;
    const int bx  = blockIdx.x & 7;
    const int by  = blockIdx.x >> 3;
    const int b   = blockIdx.y;
    const int x0  = bx * TILE, y0 = by * TILE;

    const float* fbase = g_feats + (size_t)b * NCH * HW;
    const int oy0 = grp * RPT;
    const int sx  = lx + 12;

    float acc[RPT];
    float yacc[RPT];
    {
        float bi = __ldg(bias + DI);
        float cb = convB[0];
#pragma unroll
        for (int k = 0; k < RPT; k++) { acc[k] = bi; yacc[k] = cb; }
    }

    auto stage = [&](int c, int sel) {
        const float* plane = fbase + (size_t)c * HW;
        float* dst = sbuf + sel * SBUF;
        for (int idx = tid; idx < NV4; idx += 256) {
            int sy_ = idx / (TW / 4);
            int c4  = idx - sy_ * (TW / 4);
            int gy  = y0 - D + sy_;
            int gx  = x0 - 12 + c4 * 4;
            bool ok = ((unsigned)gy < HH) && ((unsigned)gx < WW);
            const float* src = ok ? (plane + gy * WW + gx) : plane;
            unsigned sa = (unsigned)__cvta_generic_to_shared(dst + sy_ * TW + c4 * 4);
            int sz = ok ? 16 : 0;
            asm volatile("cp.async.cg.shared.global [%0], [%1], 16, %2;\n"
                         :: "r"(sa), "l"(src), "r"(sz));
        }
        asm volatile("cp.async.commit_group;\n" ::: "memory");
    };

    stage(0, 0);
    asm volatile("cp.async.wait_group 0;\n" ::: "memory");
    __syncthreads();

    int cur = 0;
    for (int c = 0; c < nin; c++) {
        if (c + 1 < nin) stage(c + 1, cur ^ 1);

        const float* wp = Wmsd + ((size_t)DI * 30 + c) * 9;
        float w0 = __ldg(wp + 0), w1 = __ldg(wp + 1), w2 = __ldg(wp + 2);
        float w3 = __ldg(wp + 3), w4 = __ldg(wp + 4), w5 = __ldg(wp + 5);
        float w6 = __ldg(wp + 6), w7 = __ldg(wp + 7), w8 = __ldg(wp + 8);
        float wF = __ldg(convW + c);

        const float* sb_ = sbuf + cur * SBUF;
#pragma unroll
        for (int rr = 0; rr < RPT + 2 * D; rr++) {
            const float* rp = sb_ + (oy0 + rr) * TW + sx;
            float v0 = rp[-D], v1 = rp[0], v2 = rp[D];
            if (rr < RPT)
                acc[rr]       = fmaf(w0, v0, fmaf(w1, v1, fmaf(w2, v2, acc[rr])));
            if (rr >= D && rr < RPT + D) {
                acc[rr - D]   = fmaf(w3, v0, fmaf(w4, v1, fmaf(w5, v2, acc[rr - D])));
                // v1 IS feats_c at pixel row (y0 + rr - D): fold final 1x1 here
                yacc[rr - D]  = fmaf(wF, v1, yacc[rr - D]);
            }
            if (rr >= 2 * D)
                acc[rr - 2*D] = fmaf(w6, v0, fmaf(w7, v1, fmaf(w8, v2, acc[rr - 2*D])));
        }

        if (c + 1 < nin)
            asm volatile("cp.async.wait_group 0;\n" ::: "memory");
        __syncthreads();
        cur ^= 1;
    }

    // h29 = relu(acc); y = (yacc + convW[30]*h29)*sw + sb -> out
    float wL = __ldg(convW + 30);
    float sw = sout_w[0], sb = sout_b[0];
    float* op = out + (size_t)b * HW + (size_t)(y0 + oy0) * WW + (x0 + lx);
#pragma unroll
    for (int k = 0; k < RPT; k++) {
        float h = fmaxf(acc[k], 0.0f);
        float y = fmaf(wL, h, yacc[k]);
        op[(size_t)k * WW] = fmaf(y, sw, sb);
    }
}

// ---------------------------------------------------------------------------
// Launch
// ---------------------------------------------------------------------------
template<int D>
static inline void launch_depth(int i, const float* Wmsd, const float* bias) {
    constexpr int TH = 64 + 2 * D;
    int sm = 2 * TH * 88 * (int)sizeof(float);
    cudaFuncSetAttribute(k_depth<D>, cudaFuncAttributeMaxDynamicSharedMemorySize, sm);
    k_depth<D><<<dim3(64, BB), 256, sm>>>(Wmsd, bias, i);
}

extern "C" void kernel_launch(void* const* d_in, const int* in_sizes, int n_in,
                              void* d_out, int out_size) {
    const float* x      = (const float*)d_in[0];
    const float* Wmsd   = (const float*)d_in[1];
    const float* bias   = (const float*)d_in[2];
    const float* convW  = (const float*)d_in[3];
    const float* convB  = (const float*)d_in[4];
    const float* sin_w  = (const float*)d_in[5];
    const float* sin_b  = (const float*)d_in[6];
    const float* sout_w = (const float*)d_in[7];
    const float* sout_b = (const float*)d_in[8];
    float* out = (float*)d_out;

    k_init<<<(BB * HW / 4) / 256, 256>>>(x, sin_w, sin_b);

    for (int i = 0; i < 29; i++) {
        int d = (i % 10) + 1;
        switch (d) {
            case  1: launch_depth< 1>(i, Wmsd, bias); break;
            case  2: launch_depth< 2>(i, Wmsd, bias); break;
            case  3: launch_depth< 3>(i, Wmsd, bias); break;
            case  4: launch_depth< 4>(i, Wmsd, bias); break;
            case  5: launch_depth< 5>(i, Wmsd, bias); break;
            case  6: launch_depth< 6>(i, Wmsd, bias); break;
            case  7: launch_depth< 7>(i, Wmsd, bias); break;
            case  8: launch_depth< 8>(i, Wmsd, bias); break;
            case  9: launch_depth< 9>(i, Wmsd, bias); break;
            default: launch_depth<10>(i, Wmsd, bias); break;
        }
    }

    // Depth 29 (D=10) with fused final 1x1 conv + affine; writes d_out.
    {
        int sm = 2 * (64 + 20) * 88 * (int)sizeof(float);
        cudaFuncSetAttribute(k_depth_last,
                             cudaFuncAttributeMaxDynamicSharedMemorySize, sm);
        k_depth_last<<<dim3(64, BB), 256, sm>>>(
            Wmsd, bias, convW, convB, sout_w, sout_b, out);
    }
}

// round 14
// speedup vs baseline: 1.1911x; 1.1911x over previous
#include <cuda_runtime.h>
#include <cstdint>

#define HH 512
#define WW 512
#define BB 4
#define NCH 31          // IN_C + DEPTH
#define HW (HH * WW)

// Scratch: feats tensor [B][31][H][W]  (130 MB device global; written before read)
__device__ float g_feats[(size_t)BB * NCH * HW];

// ---------------------------------------------------------------------------
// Init: feats[:,0] = x * sin_w + sin_b   (float4 vectorized)
// ---------------------------------------------------------------------------
__global__ void k_init(const float* __restrict__ x,
                       const float* __restrict__ sin_w,
                       const float* __restrict__ sin_b) {
    int idx = blockIdx.x * blockDim.x + threadIdx.x;   // 0 .. BB*HW/4-1
    float w = sin_w[0], b = sin_b[0];
    int bb = idx >> 16;            // HW/4 = 65536
    int p  = idx & 65535;
    float4 v = reinterpret_cast<const float4*>(x)[idx];
    float4 r = make_float4(fmaf(v.x, w, b), fmaf(v.y, w, b),
                           fmaf(v.z, w, b), fmaf(v.w, w, b));
    reinterpret_cast<float4*>(g_feats)[(size_t)(bb * NCH) * (HW / 4) + p] = r;
}

// ---------------------------------------------------------------------------
// Depth kernel, templated on dilation D.
// Block: 256 threads, output tile 64 wide x 64 tall.
// Thread = 1 column x 16 rows (4 row groups of 64 columns).
// Staging: fixed 96-float-wide aligned window [x0-16, x0+80) x [y0-D, y0+64+D)
// via 16-byte cp.async (zfill for padding), double-buffered across channels.
// Compute: vertical register window — each loaded (v-D, v0, v+D) triple feeds
// up to 3 output-row accumulators.
// ---------------------------------------------------------------------------
template<int D>
__global__ void __launch_bounds__(256)
k_depth(const float* __restrict__ Wmsd,
        const float* __restrict__ bias,
        int di) {
    constexpr int TILE = 64;
    constexpr int RPT  = 16;              // output rows per thread
    constexpr int TW   = 96;              // staged window width (floats, 16B-aligned)
    constexpr int TH   = TILE + 2 * D;    // staged window height
    constexpr int SBUF = TH * TW;
    constexpr int NV4  = TH * (TW / 4);   // float4 chunks per channel tile

    extern __shared__ float sbuf[];       // 2 buffers of SBUF floats

    const int nin = di + 1;               // input channels this depth
    const int tid = threadIdx.x;
    const int lx  = tid & 63;             // tile-local x (column)
    const int grp = tid >> 6;             // 0..3 -> row group
    const int bx  = blockIdx.x & 7;
    const int by  = blockIdx.x >> 3;
    const int b   = blockIdx.y;
    const int x0  = bx * TILE, y0 = by * TILE;

    const float* fbase = g_feats + (size_t)b * NCH * HW;
    const int oy0 = grp * RPT;
    const int sx  = lx + 16;              // smem x of this thread's column

    float acc[RPT];
    float bi = __ldg(bias + di);
#pragma unroll
    for (int k = 0; k < RPT; k++) acc[k] = bi;

    auto stage = [&](int c, int sel) {
        const float* plane = fbase + (size_t)c * HW;
        float* dst = sbuf + sel * SBUF;
        for (int idx = tid; idx < NV4; idx += 256) {
            int sy_ = idx / (TW / 4);
            int c4  = idx - sy_ * (TW / 4);
            int gy  = y0 - D + sy_;
            int gx  = x0 - 16 + c4 * 4;
            // 4-float chunks are 4-aligned and the image width is a multiple of
            // 4, so a chunk is either fully inside or fully outside -> zfill.
            bool ok = ((unsigned)gy < HH) && ((unsigned)gx < WW);
            const float* src = ok ? (plane + gy * WW + gx) : plane;
            unsigned sa = (unsigned)__cvta_generic_to_shared(dst + sy_ * TW + c4 * 4);
            int sz = ok ? 16 : 0;
            asm volatile("cp.async.cg.shared.global [%0], [%1], 16, %2;\n"
                         :: "r"(sa), "l"(src), "r"(sz));
        }
        asm volatile("cp.async.commit_group;\n" ::: "memory");
    };

    // Prologue: stage channel 0 into buffer 0
    stage(0, 0);
    asm volatile("cp.async.wait_group 0;\n" ::: "memory");
    __syncthreads();

    int cur = 0;
    for (int c = 0; c < nin; c++) {
        if (c + 1 < nin) stage(c + 1, cur ^ 1);   // overlap next stage with compute

        const float* wp = Wmsd + ((size_t)di * 30 + c) * 9;
        float w0 = __ldg(wp + 0), w1 = __ldg(wp + 1), w2 = __ldg(wp + 2);
        float w3 = __ldg(wp + 3), w4 = __ldg(wp + 4), w5 = __ldg(wp + 5);
        float w6 = __ldg(wp + 6), w7 = __ldg(wp + 7), w8 = __ldg(wp + 8);

        const float* sb_ = sbuf + cur * SBUF;
#pragma unroll
        for (int rr = 0; rr < RPT + 2 * D; rr++) {
            const float* rp = sb_ + (oy0 + rr) * TW + sx;
            float v0 = rp[-D], v1 = rp[0], v2 = rp[D];
            // input row (rel) ir = rr - D contributes to:
            //   out row rr      with weight row 0 (tap at -D)
            //   out row rr - D  with weight row 1 (tap at  0)
            //   out row rr - 2D with weight row 2 (tap at +D)
            if (rr < RPT)
                acc[rr]       = fmaf(w0, v0, fmaf(w1, v1, fmaf(w2, v2, acc[rr])));
            if (rr >= D && rr < RPT + D)
                acc[rr - D]   = fmaf(w3, v0, fmaf(w4, v1, fmaf(w5, v2, acc[rr - D])));
            if (rr >= 2 * D)
                acc[rr - 2*D] = fmaf(w6, v0, fmaf(w7, v1, fmaf(w8, v2, acc[rr - 2*D])));
        }

        if (c + 1 < nin)
            asm volatile("cp.async.wait_group 0;\n" ::: "memory");
        __syncthreads();
        cur ^= 1;
    }

    // ReLU + store new channel (index nin = di+1)
    float* op = g_feats + (size_t)b * NCH * HW + (size_t)nin * HW
              + (size_t)(y0 + oy0) * WW + (x0 + lx);
#pragma unroll
    for (int k = 0; k < RPT; k++)
        op[(size_t)k * WW] = fmaxf(acc[k], 0.0f);
}

// ---------------------------------------------------------------------------
// Final 1x1 conv over 31 channels + convB, then sout affine (float4)
// ---------------------------------------------------------------------------
__global__ void k_final(const float* __restrict__ convW,
                        const float* __restrict__ convB,
                        const float* __restrict__ sout_w,
                        const float* __restrict__ sout_b,
                        float* __restrict__ out) {
    int idx = blockIdx.x * blockDim.x + threadIdx.x;   // 0 .. BB*HW/4-1
    int bb = idx >> 16;
    int p  = idx & 65535;
    const float4* f4 = reinterpret_cast<const float4*>(g_feats)
                     + (size_t)(bb * NCH) * (HW / 4) + p;
    float cb = convB[0];
    float4 a = make_float4(cb, cb, cb, cb);
#pragma unroll 4
    for (int c = 0; c < NCH; c++) {
        float wc = __ldg(convW + c);
        float4 v = __ldg(f4 + (size_t)c * (HW / 4));
        a.x = fmaf(wc, v.x, a.x);
        a.y = fmaf(wc, v.y, a.y);
        a.z = fmaf(wc, v.z, a.z);
        a.w = fmaf(wc, v.w, a.w);
    }
    float sw = sout_w[0], sb = sout_b[0];
    float4 r = make_float4(fmaf(a.x, sw, sb), fmaf(a.y, sw, sb),
                           fmaf(a.z, sw, sb), fmaf(a.w, sw, sb));
    reinterpret_cast<float4*>(out)[idx] = r;
}

// ---------------------------------------------------------------------------
// Launch
// ---------------------------------------------------------------------------
template<int D>
static inline void launch_depth(int i, const float* Wmsd, const float* bias) {
    constexpr int TH = 64 + 2 * D;
    int sm = 2 * TH * 96 * (int)sizeof(float);
    cudaFuncSetAttribute(k_depth<D>, cudaFuncAttributeMaxDynamicSharedMemorySize, sm);
    k_depth<D><<<dim3(64, BB), 256, sm>>>(Wmsd, bias, i);
}

extern "C" void kernel_launch(void* const* d_in, const int* in_sizes, int n_in,
                              void* d_out, int out_size) {
    const float* x      = (const float*)d_in[0];
    const float* Wmsd   = (const float*)d_in[1];
    const float* bias   = (const float*)d_in[2];
    const float* convW  = (const float*)d_in[3];
    const float* convB  = (const float*)d_in[4];
    const float* sin_w  = (const float*)d_in[5];
    const float* sin_b  = (const float*)d_in[6];
    const float* sout_w = (const float*)d_in[7];
    const float* sout_b = (const float*)d_in[8];
    float* out = (float*)d_out;

    k_init<<<(BB * HW / 4) / 256, 256>>>(x, sin_w, sin_b);

    for (int i = 0; i < 30; i++) {
        int d = (i % 10) + 1;
        switch (d) {
            case  1: launch_depth< 1>(i, Wmsd, bias); break;
            case  2: launch_depth< 2>(i, Wmsd, bias); break;
            case  3: launch_depth< 3>(i, Wmsd, bias); break;
            case  4: launch_depth< 4>(i, Wmsd, bias); break;
            case  5: launch_depth< 5>(i, Wmsd, bias); break;
            case  6: launch_depth< 6>(i, Wmsd, bias); break;
            case  7: launch_depth< 7>(i, Wmsd, bias); break;
            case  8: launch_depth< 8>(i, Wmsd, bias); break;
            case  9: launch_depth< 9>(i, Wmsd, bias); break;
            default: launch_depth<10>(i, Wmsd, bias); break;
        }
    }

    k_final<<<(BB * HW / 4) / 256, 256>>>(convW, convB, sout_w, sout_b, out);
}

// round 15
// speedup vs baseline: 1.2302x; 1.0328x over previous
#include <cuda_runtime.h>
#include <cstdint>

#define HH 512
#define WW 512
#define BB 4
#define NCH 31          // IN_C + DEPTH
#define HW (HH * WW)

// Scratch: feats tensor [B][31][H][W]  (130 MB device global; written before read)
__device__ float g_feats[(size_t)BB * NCH * HW];

// ---------------------------------------------------------------------------
// Init: feats[:,0] = x * sin_w + sin_b   (float4 vectorized)
// ---------------------------------------------------------------------------
__global__ void k_init(const float* __restrict__ x,
                       const float* __restrict__ sin_w,
                       const float* __restrict__ sin_b) {
    int idx = blockIdx.x * blockDim.x + threadIdx.x;   // 0 .. BB*HW/4-1
    float w = sin_w[0], b = sin_b[0];
    int bb = idx >> 16;            // HW/4 = 65536
    int p  = idx & 65535;
    float4 v = reinterpret_cast<const float4*>(x)[idx];
    float4 r = make_float4(fmaf(v.x, w, b), fmaf(v.y, w, b),
                           fmaf(v.z, w, b), fmaf(v.w, w, b));
    reinterpret_cast<float4*>(g_feats)[(size_t)(bb * NCH) * (HW / 4) + p] = r;
}

// ---------------------------------------------------------------------------
// Depth kernel (depths 0..28) — TRUE champion (TW=96, 64B-aligned window).
// Block: 256 threads, output tile 64x64; thread = 1 column x 16 rows.
// Staging: 96-float-wide window [x0-16, x0+80) x [y0-D, y0+64+D) via 16B
// cp.async (zfill padding) — row starts are 64B-aligned so every chunk lands
// in aligned 128B segments. Double-buffered across channels.
// ---------------------------------------------------------------------------
template<int D>
__global__ void __launch_bounds__(256)
k_depth(const float* __restrict__ Wmsd,
        const float* __restrict__ bias,
        int di) {
    constexpr int TILE = 64;
    constexpr int RPT  = 16;              // output rows per thread
    constexpr int TW   = 96;              // staged window width (floats)
    constexpr int TH   = TILE + 2 * D;    // staged window height
    constexpr int SBUF = TH * TW;
    constexpr int NV4  = TH * (TW / 4);   // float4 chunks per channel tile

    extern __shared__ float sbuf[];       // 2 buffers of SBUF floats

    const int nin = di + 1;               // input channels this depth
    const int tid = threadIdx.x;
    const int lx  = tid & 63;             // tile-local x (column)
    const int grp = tid >> 6;             // 0..3 -> row group
    const int bx  = blockIdx.x & 7;
    const int by  = blockIdx.x >> 3;
    const int b   = blockIdx.y;
    const int x0  = bx * TILE, y0 = by * TILE;

    const float* fbase = g_feats + (size_t)b * NCH * HW;
    const int oy0 = grp * RPT;
    const int sx  = lx + 16;              // smem x of this thread's column

    float acc[RPT];
    float bi = __ldg(bias + di);
#pragma unroll
    for (int k = 0; k < RPT; k++) acc[k] = bi;

    auto stage = [&](int c, int sel) {
        const float* plane = fbase + (size_t)c * HW;
        float* dst = sbuf + sel * SBUF;
        for (int idx = tid; idx < NV4; idx += 256) {
            int sy_ = idx / (TW / 4);
            int c4  = idx - sy_ * (TW / 4);
            int gy  = y0 - D + sy_;
            int gx  = x0 - 16 + c4 * 4;
            // 4-float chunks are 4-aligned and the image width is a multiple of
            // 4, so a chunk is either fully inside or fully outside -> zfill.
            bool ok = ((unsigned)gy < HH) && ((unsigned)gx < WW);
            const float* src = ok ? (plane + gy * WW + gx) : plane;
            unsigned sa = (unsigned)__cvta_generic_to_shared(dst + sy_ * TW + c4 * 4);
            int sz = ok ? 16 : 0;
            asm volatile("cp.async.cg.shared.global [%0], [%1], 16, %2;\n"
                         :: "r"(sa), "l"(src), "r"(sz));
        }
        asm volatile("cp.async.commit_group;\n" ::: "memory");
    };

    // Prologue: stage channel 0 into buffer 0
    stage(0, 0);
    asm volatile("cp.async.wait_group 0;\n" ::: "memory");
    __syncthreads();

    int cur = 0;
    for (int c = 0; c < nin; c++) {
        if (c + 1 < nin) stage(c + 1, cur ^ 1);   // overlap next stage with compute

        const float* wp = Wmsd + ((size_t)di * 30 + c) * 9;
        float w0 = __ldg(wp + 0), w1 = __ldg(wp + 1), w2 = __ldg(wp + 2);
        float w3 = __ldg(wp + 3), w4 = __ldg(wp + 4), w5 = __ldg(wp + 5);
        float w6 = __ldg(wp + 6), w7 = __ldg(wp + 7), w8 = __ldg(wp + 8);

        const float* sb_ = sbuf + cur * SBUF;
#pragma unroll
        for (int rr = 0; rr < RPT + 2 * D; rr++) {
            const float* rp = sb_ + (oy0 + rr) * TW + sx;
            float v0 = rp[-D], v1 = rp[0], v2 = rp[D];
            // input row rr-D feeds out rows rr (w-row0), rr-D (w-row1),
            // rr-2D (w-row2)
            if (rr < RPT)
                acc[rr]       = fmaf(w0, v0, fmaf(w1, v1, fmaf(w2, v2, acc[rr])));
            if (rr >= D && rr < RPT + D)
                acc[rr - D]   = fmaf(w3, v0, fmaf(w4, v1, fmaf(w5, v2, acc[rr - D])));
            if (rr >= 2 * D)
                acc[rr - 2*D] = fmaf(w6, v0, fmaf(w7, v1, fmaf(w8, v2, acc[rr - 2*D])));
        }

        if (c + 1 < nin)
            asm volatile("cp.async.wait_group 0;\n" ::: "memory");
        __syncthreads();
        cur ^= 1;
    }

    // ReLU + store new channel (index nin = di+1)
    float* op = g_feats + (size_t)b * NCH * HW + (size_t)nin * HW
              + (size_t)(y0 + oy0) * WW + (x0 + lx);
#pragma unroll
    for (int k = 0; k < RPT; k++)
        op[(size_t)k * WW] = fmaxf(acc[k], 0.0f);
}

// ---------------------------------------------------------------------------
// LAST depth kernel (depth 29, D=10, nin=30), TW=96 base, with the final 1x1
// conv fused: while each channel tile c sits in smem, fold
//   yacc[k] += convW[c] * feats_c(pixel)      (reuses the loaded center tap)
// After the channel loop, h29 exists only in registers:
//   y = (yacc + convW[30]*relu(h29) (+convB)) * sout_w + sout_b -> d_out.
// Deletes the standalone k_final pass (130MB read + 4MB write) and the 4MB
// h29 store.
// ---------------------------------------------------------------------------
__global__ void __launch_bounds__(256)
k_depth_last(const float* __restrict__ Wmsd,
             const float* __restrict__ bias,
             const float* __restrict__ convW,
             const float* __restrict__ convB,
             const float* __restrict__ sout_w,
             const float* __restrict__ sout_b,
             float* __restrict__ out) {
    constexpr int D    = 10;
    constexpr int DI   = 29;
    constexpr int TILE = 64;
    constexpr int RPT  = 16;
    constexpr int TW   = 96;
    constexpr int TH   = TILE + 2 * D;
    constexpr int SBUF = TH * TW;
    constexpr int NV4  = TH * (TW / 4);

    extern __shared__ float sbuf[];

    const int nin = DI + 1;               // 30
    const int tid = threadIdx.x;
    const int lx  = tid & 63;
    const int grp = tid >> 6;
    const int bx  = blockIdx.x & 7;
    const int by  = blockIdx.x >> 3;
    const int b   = blockIdx.y;
    const int x0  = bx * TILE, y0 = by * TILE;

    const float* fbase = g_feats + (size_t)b * NCH * HW;
    const int oy0 = grp * RPT;
    const int sx  = lx + 16;

    float acc[RPT];
    float yacc[RPT];
    {
        float bi = __ldg(bias + DI);
        float cb = convB[0];
#pragma unroll
        for (int k = 0; k < RPT; k++) { acc[k] = bi; yacc[k] = cb; }
    }

    auto stage = [&](int c, int sel) {
        const float* plane = fbase + (size_t)c * HW;
        float* dst = sbuf + sel * SBUF;
        for (int idx = tid; idx < NV4; idx += 256) {
            int sy_ = idx / (TW / 4);
            int c4  = idx - sy_ * (TW / 4);
            int gy  = y0 - D + sy_;
            int gx  = x0 - 16 + c4 * 4;
            bool ok = ((unsigned)gy < HH) && ((unsigned)gx < WW);
            const float* src = ok ? (plane + gy * WW + gx) : plane;
            unsigned sa = (unsigned)__cvta_generic_to_shared(dst + sy_ * TW + c4 * 4);
            int sz = ok ? 16 : 0;
            asm volatile("cp.async.cg.shared.global [%0], [%1], 16, %2;\n"
                         :: "r"(sa), "l"(src), "r"(sz));
        }
        asm volatile("cp.async.commit_group;\n" ::: "memory");
    };

    stage(0, 0);
    asm volatile("cp.async.wait_group 0;\n" ::: "memory");
    __syncthreads();

    int cur = 0;
    for (int c = 0; c < nin; c++) {
        if (c + 1 < nin) stage(c + 1, cur ^ 1);

        const float* wp = Wmsd + ((size_t)DI * 30 + c) * 9;
        float w0 = __ldg(wp + 0), w1 = __ldg(wp + 1), w2 = __ldg(wp + 2);
        float w3 = __ldg(wp + 3), w4 = __ldg(wp + 4), w5 = __ldg(wp + 5);
        float w6 = __ldg(wp + 6), w7 = __ldg(wp + 7), w8 = __ldg(wp + 8);
        float wF = __ldg(convW + c);

        const float* sb_ = sbuf + cur * SBUF;
#pragma unroll
        for (int rr = 0; rr < RPT + 2 * D; rr++) {
            const float* rp = sb_ + (oy0 + rr) * TW + sx;
            float v0 = rp[-D], v1 = rp[0], v2 = rp[D];
            if (rr < RPT)
                acc[rr]       = fmaf(w0, v0, fmaf(w1, v1, fmaf(w2, v2, acc[rr])));
            if (rr >= D && rr < RPT + D) {
                acc[rr - D]   = fmaf(w3, v0, fmaf(w4, v1, fmaf(w5, v2, acc[rr - D])));
                // v1 IS feats_c at output pixel row (y0+oy0+rr-D): fold 1x1
                yacc[rr - D]  = fmaf(wF, v1, yacc[rr - D]);
            }
            if (rr >= 2 * D)
                acc[rr - 2*D] = fmaf(w6, v0, fmaf(w7, v1, fmaf(w8, v2, acc[rr - 2*D])));
        }

        if (c + 1 < nin)
            asm volatile("cp.async.wait_group 0;\n" ::: "memory");
        __syncthreads();
        cur ^= 1;
    }

    // h29 = relu(acc); y = (yacc + convW[30]*h29)*sw + sb -> out
    float wL = __ldg(convW + 30);
    float sw = sout_w[0], sb = sout_b[0];
    float* op = out + (size_t)b * HW + (size_t)(y0 + oy0) * WW + (x0 + lx);
#pragma unroll
    for (int k = 0; k < RPT; k++) {
        float h = fmaxf(acc[k], 0.0f);
        float y = fmaf(wL, h, yacc[k]);
        op[(size_t)k * WW] = fmaf(y, sw, sb);
    }
}

// ---------------------------------------------------------------------------
// Launch
// ---------------------------------------------------------------------------
template<int D>
static inline void launch_depth(int i, const float* Wmsd, const float* bias) {
    constexpr int TH = 64 + 2 * D;
    int sm = 2 * TH * 96 * (int)sizeof(float);
    cudaFuncSetAttribute(k_depth<D>, cudaFuncAttributeMaxDynamicSharedMemorySize, sm);
    k_depth<D><<<dim3(64, BB), 256, sm>>>(Wmsd, bias, i);
}

extern "C" void kernel_launch(void* const* d_in, const int* in_sizes, int n_in,
                              void* d_out, int out_size) {
    const float* x      = (const float*)d_in[0];
    const float* Wmsd   = (const float*)d_in[1];
    const float* bias   = (const float*)d_in[2];
    const float* convW  = (const float*)d_in[3];
    const float* convB  = (const float*)d_in[4];
    const float* sin_w  = (const float*)d_in[5];
    const float* sin_b  = (const float*)d_in[6];
    const float* sout_w = (const float*)d_in[7];
    const float* sout_b = (const float*)d_in[8];
    float* out = (float*)d_out;

    k_init<<<(BB * HW / 4) / 256, 256>>>(x, sin_w, sin_b);

    for (int i = 0; i < 29; i++) {
        int d = (i % 10) + 1;
        switch (d) {
            case  1: launch_depth< 1>(i, Wmsd, bias); break;
            case  2: launch_depth< 2>(i, Wmsd, bias); break;
            case  3: launch_depth< 3>(i, Wmsd, bias); break;
            case  4: launch_depth< 4>(i, Wmsd, bias); break;
            case  5: launch_depth< 5>(i, Wmsd, bias); break;
            case  6: launch_depth< 6>(i, Wmsd, bias); break;
            case  7: launch_depth< 7>(i, Wmsd, bias); break;
            case  8: launch_depth< 8>(i, Wmsd, bias); break;
            case  9: launch_depth< 9>(i, Wmsd, bias); break;
            default: launch_depth<10>(i, Wmsd, bias); break;
        }
    }

    // Depth 29 (D=10) with fused final 1x1 conv + affine; writes d_out.
    {
        int sm = 2 * (64 + 20) * 96 * (int)sizeof(float);
        cudaFuncSetAttribute(k_depth_last,
                             cudaFuncAttributeMaxDynamicSharedMemorySize, sm);
        k_depth_last<<<dim3(64, BB), 256, sm>>>(
            Wmsd, bias, convW, convB, sout_w, sout_b, out);
    }
}

// round 16
// speedup vs baseline: 1.2719x; 1.0339x over previous
#include <cuda_runtime.h>
#include <cstdint>

#define HH 512
#define WW 512
#define BB 4
#define NCH 31          // IN_C + DEPTH
#define HW (HH * WW)

// Scratch: feats tensor [B][31][H][W]  (130 MB device global; written before read)
__device__ float g_feats[(size_t)BB * NCH * HW];

// ---------------------------------------------------------------------------
// Init: feats[:,0] = x * sin_w + sin_b   (float4 vectorized)
// ---------------------------------------------------------------------------
__global__ void k_init(const float* __restrict__ x,
                       const float* __restrict__ sin_w,
                       const float* __restrict__ sin_b) {
    int idx = blockIdx.x * blockDim.x + threadIdx.x;   // 0 .. BB*HW/4-1
    float w = sin_w[0], b = sin_b[0];
    int bb = idx >> 16;            // HW/4 = 65536
    int p  = idx & 65535;
    float4 v = reinterpret_cast<const float4*>(x)[idx];
    float4 r = make_float4(fmaf(v.x, w, b), fmaf(v.y, w, b),
                           fmaf(v.z, w, b), fmaf(v.w, w, b));
    reinterpret_cast<float4*>(g_feats)[(size_t)(bb * NCH) * (HW / 4) + p] = r;
}

// ---------------------------------------------------------------------------
// Depth kernel (depths 0..28) — TW=96 champion + TRIPLE-buffered staging.
// Block: 256 threads, output tile 64x64; thread = 1 column x 16 rows.
// Staging: 96-float-wide window [x0-16, x0+80) x [y0-D, y0+64+D) via 16B
// cp.async (zfill padding; row starts 64B-aligned). Triple-buffered:
// stage(c+2) issued at the top of compute(c); wait_group 1 targets a copy
// that has had ~2 full compute phases to land. 100% smem carveout keeps
// 2 CTAs/SM at every D (3 x 96.8KB x 2 = 193.5KB <= 228KB worst case).
// ---------------------------------------------------------------------------
template<int D>
__global__ void __launch_bounds__(256, 2)
k_depth(const float* __restrict__ Wmsd,
        const float* __restrict__ bias,
        int di) {
    constexpr int TILE = 64;
    constexpr int RPT  = 16;              // output rows per thread
    constexpr int TW   = 96;              // staged window width (floats)
    constexpr int TH   = TILE + 2 * D;    // staged window height
    constexpr int SBUF = TH * TW;
    constexpr int NV4  = TH * (TW / 4);   // float4 chunks per channel tile

    extern __shared__ float sbuf[];       // 3 buffers of SBUF floats

    const int nin = di + 1;               // input channels this depth
    const int tid = threadIdx.x;
    const int lx  = tid & 63;             // tile-local x (column)
    const int grp = tid >> 6;             // 0..3 -> row group
    const int bx  = blockIdx.x & 7;
    const int by  = blockIdx.x >> 3;
    const int b   = blockIdx.y;
    const int x0  = bx * TILE, y0 = by * TILE;

    const float* fbase = g_feats + (size_t)b * NCH * HW;
    const int oy0 = grp * RPT;
    const int sx  = lx + 16;              // smem x of this thread's column

    float acc[RPT];
    float bi = __ldg(bias + di);
#pragma unroll
    for (int k = 0; k < RPT; k++) acc[k] = bi;

    auto stage = [&](int c, int sel) {
        const float* plane = fbase + (size_t)c * HW;
        float* dst = sbuf + sel * SBUF;
        for (int idx = tid; idx < NV4; idx += 256) {
            int sy_ = idx / (TW / 4);
            int c4  = idx - sy_ * (TW / 4);
            int gy  = y0 - D + sy_;
            int gx  = x0 - 16 + c4 * 4;
            // 4-float chunks are 4-aligned and the image width is a multiple of
            // 4, so a chunk is either fully inside or fully outside -> zfill.
            bool ok = ((unsigned)gy < HH) && ((unsigned)gx < WW);
            const float* src = ok ? (plane + gy * WW + gx) : plane;
            unsigned sa = (unsigned)__cvta_generic_to_shared(dst + sy_ * TW + c4 * 4);
            int sz = ok ? 16 : 0;
            asm volatile("cp.async.cg.shared.global [%0], [%1], 16, %2;\n"
                         :: "r"(sa), "l"(src), "r"(sz));
        }
        asm volatile("cp.async.commit_group;\n" ::: "memory");
    };

    // Prologue: stage channels 0 and 1
    stage(0, 0);
    if (nin > 1) stage(1, 1);

    int cur = 0;   // = c % 3
    for (int c = 0; c < nin; c++) {
        // Weight loads first — LDG latency overlaps the wait below.
        const float* wp = Wmsd + ((size_t)di * 30 + c) * 9;
        float w0 = __ldg(wp + 0), w1 = __ldg(wp + 1), w2 = __ldg(wp + 2);
        float w3 = __ldg(wp + 3), w4 = __ldg(wp + 4), w5 = __ldg(wp + 5);
        float w6 = __ldg(wp + 6), w7 = __ldg(wp + 7), w8 = __ldg(wp + 8);

        // Ensure stage(c) has landed. At most stage(c+1) may remain in flight.
        if (c + 1 < nin)
            asm volatile("cp.async.wait_group 1;\n" ::: "memory");
        else
            asm volatile("cp.async.wait_group 0;\n" ::: "memory");
        __syncthreads();   // copies visible block-wide; all threads past compute(c-1)

        // Stage c+2 into buffer (c+2)%3 — last read by compute(c-1), which the
        // barrier above just retired. Lands during compute(c)+compute(c+1).
        if (c + 2 < nin) {
            int sel2 = cur + 2; if (sel2 >= 3) sel2 -= 3;
            stage(c + 2, sel2);
        }

        const float* sb_ = sbuf + cur * SBUF;
#pragma unroll
        for (int rr = 0; rr < RPT + 2 * D; rr++) {
            const float* rp = sb_ + (oy0 + rr) * TW + sx;
            float v0 = rp[-D], v1 = rp[0], v2 = rp[D];
            // input row rr-D feeds out rows rr (w-row0), rr-D (w-row1),
            // rr-2D (w-row2)
            if (rr < RPT)
                acc[rr]       = fmaf(w0, v0, fmaf(w1, v1, fmaf(w2, v2, acc[rr])));
            if (rr >= D && rr < RPT + D)
                acc[rr - D]   = fmaf(w3, v0, fmaf(w4, v1, fmaf(w5, v2, acc[rr - D])));
            if (rr >= 2 * D)
                acc[rr - 2*D] = fmaf(w6, v0, fmaf(w7, v1, fmaf(w8, v2, acc[rr - 2*D])));
        }

        cur++; if (cur >= 3) cur = 0;
    }

    // ReLU + store new channel (index nin = di+1)
    float* op = g_feats + (size_t)b * NCH * HW + (size_t)nin * HW
              + (size_t)(y0 + oy0) * WW + (x0 + lx);
#pragma unroll
    for (int k = 0; k < RPT; k++)
        op[(size_t)k * WW] = fmaxf(acc[k], 0.0f);
}

// ---------------------------------------------------------------------------
// LAST depth kernel (depth 29, D=10, nin=30), TW=96, triple-buffered, with
// the final 1x1 conv fused (reuses the loaded center tap v1):
//   y = (yacc + convW[30]*relu(h29) + convB) * sout_w + sout_b -> d_out.
// h29 never touches global memory; the standalone k_final pass is deleted.
// ---------------------------------------------------------------------------
__global__ void __launch_bounds__(256, 2)
k_depth_last(const float* __restrict__ Wmsd,
             const float* __restrict__ bias,
             const float* __restrict__ convW,
             const float* __restrict__ convB,
             const float* __restrict__ sout_w,
             const float* __restrict__ sout_b,
             float* __restrict__ out) {
    constexpr int D    = 10;
    constexpr int DI   = 29;
    constexpr int TILE = 64;
    constexpr int RPT  = 16;
    constexpr int TW   = 96;
    constexpr int TH   = TILE + 2 * D;
    constexpr int SBUF = TH * TW;
    constexpr int NV4  = TH * (TW / 4);

    extern __shared__ float sbuf[];       // 3 buffers

    const int nin = DI + 1;               // 30
    const int tid = threadIdx.x;
    const int lx  = tid & 63;
    const int grp = tid >> 6;
    const int bx  = blockIdx.x & 7;
    const int by  = blockIdx.x >> 3;
    const int b   = blockIdx.y;
    const int x0  = bx * TILE, y0 = by * TILE;

    const float* fbase = g_feats + (size_t)b * NCH * HW;
    const int oy0 = grp * RPT;
    const int sx  = lx + 16;

    float acc[RPT];
    float yacc[RPT];
    {
        float bi = __ldg(bias + DI);
        float cb = convB[0];
#pragma unroll
        for (int k = 0; k < RPT; k++) { acc[k] = bi; yacc[k] = cb; }
    }

    auto stage = [&](int c, int sel) {
        const float* plane = fbase + (size_t)c * HW;
        float* dst = sbuf + sel * SBUF;
        for (int idx = tid; idx < NV4; idx += 256) {
            int sy_ = idx / (TW / 4);
            int c4  = idx - sy_ * (TW / 4);
            int gy  = y0 - D + sy_;
            int gx  = x0 - 16 + c4 * 4;
            bool ok = ((unsigned)gy < HH) && ((unsigned)gx < WW);
            const float* src = ok ? (plane + gy * WW + gx) : plane;
            unsigned sa = (unsigned)__cvta_generic_to_shared(dst + sy_ * TW + c4 * 4);
            int sz = ok ? 16 : 0;
            asm volatile("cp.async.cg.shared.global [%0], [%1], 16, %2;\n"
                         :: "r"(sa), "l"(src), "r"(sz));
        }
        asm volatile("cp.async.commit_group;\n" ::: "memory");
    };

    stage(0, 0);
    stage(1, 1);

    int cur = 0;
    for (int c = 0; c < nin; c++) {
        const float* wp = Wmsd + ((size_t)DI * 30 + c) * 9;
        float w0 = __ldg(wp + 0), w1 = __ldg(wp + 1), w2 = __ldg(wp + 2);
        float w3 = __ldg(wp + 3), w4 = __ldg(wp + 4), w5 = __ldg(wp + 5);
        float w6 = __ldg(wp + 6), w7 = __ldg(wp + 7), w8 = __ldg(wp + 8);
        float wF = __ldg(convW + c);

        if (c + 1 < nin)
            asm volatile("cp.async.wait_group 1;\n" ::: "memory");
        else
            asm volatile("cp.async.wait_group 0;\n" ::: "memory");
        __syncthreads();

        if (c + 2 < nin) {
            int sel2 = cur + 2; if (sel2 >= 3) sel2 -= 3;
            stage(c + 2, sel2);
        }

        const float* sb_ = sbuf + cur * SBUF;
#pragma unroll
        for (int rr = 0; rr < RPT + 2 * D; rr++) {
            const float* rp = sb_ + (oy0 + rr) * TW + sx;
            float v0 = rp[-D], v1 = rp[0], v2 = rp[D];
            if (rr < RPT)
                acc[rr]       = fmaf(w0, v0, fmaf(w1, v1, fmaf(w2, v2, acc[rr])));
            if (rr >= D && rr < RPT + D) {
                acc[rr - D]   = fmaf(w3, v0, fmaf(w4, v1, fmaf(w5, v2, acc[rr - D])));
                // v1 IS feats_c at output pixel row (y0+oy0+rr-D): fold 1x1
                yacc[rr - D]  = fmaf(wF, v1, yacc[rr - D]);
            }
            if (rr >= 2 * D)
                acc[rr - 2*D] = fmaf(w6, v0, fmaf(w7, v1, fmaf(w8, v2, acc[rr - 2*D])));
        }

        cur++; if (cur >= 3) cur = 0;
    }

    // h29 = relu(acc); y = (yacc + convW[30]*h29)*sw + sb -> out
    float wL = __ldg(convW + 30);
    float sw = sout_w[0], sb = sout_b[0];
    float* op = out + (size_t)b * HW + (size_t)(y0 + oy0) * WW + (x0 + lx);
#pragma unroll
    for (int k = 0; k < RPT; k++) {
        float h = fmaxf(acc[k], 0.0f);
        float y = fmaf(wL, h, yacc[k]);
        op[(size_t)k * WW] = fmaf(y, sw, sb);
    }
}

// ---------------------------------------------------------------------------
// Launch
// ---------------------------------------------------------------------------
template<int D>
static inline void launch_depth(int i, const float* Wmsd, const float* bias) {
    constexpr int TH = 64 + 2 * D;
    int sm = 3 * TH * 96 * (int)sizeof(float);
    cudaFuncSetAttribute(k_depth<D>, cudaFuncAttributeMaxDynamicSharedMemorySize, sm);
    cudaFuncSetAttribute(k_depth<D>,
                         cudaFuncAttributePreferredSharedMemoryCarveout, 100);
    k_depth<D><<<dim3(64, BB), 256, sm>>>(Wmsd, bias, i);
}

extern "C" void kernel_launch(void* const* d_in, const int* in_sizes, int n_in,
                              void* d_out, int out_size) {
    const float* x      = (const float*)d_in[0];
    const float* Wmsd   = (const float*)d_in[1];
    const float* bias   = (const float*)d_in[2];
    const float* convW  = (const float*)d_in[3];
    const float* convB  = (const float*)d_in[4];
    const float* sin_w  = (const float*)d_in[5];
    const float* sin_b  = (const float*)d_in[6];
    const float* sout_w = (const float*)d_in[7];
    const float* sout_b = (const float*)d_in[8];
    float* out = (float*)d_out;

    k_init<<<(BB * HW / 4) / 256, 256>>>(x, sin_w, sin_b);

    for (int i = 0; i < 29; i++) {
        int d = (i % 10) + 1;
        switch (d) {
            case  1: launch_depth< 1>(i, Wmsd, bias); break;
            case  2: launch_depth< 2>(i, Wmsd, bias); break;
            case  3: launch_depth< 3>(i, Wmsd, bias); break;
            case  4: launch_depth< 4>(i, Wmsd, bias); break;
            case  5: launch_depth< 5>(i, Wmsd, bias); break;
            case  6: launch_depth< 6>(i, Wmsd, bias); break;
            case  7: launch_depth< 7>(i, Wmsd, bias); break;
            case  8: launch_depth< 8>(i, Wmsd, bias); break;
            case  9: launch_depth< 9>(i, Wmsd, bias); break;
            default: launch_depth<10>(i, Wmsd, bias); break;
        }
    }

    // Depth 29 (D=10) with fused final 1x1 conv + affine; writes d_out.
    {
        int sm = 3 * (64 + 20) * 96 * (int)sizeof(float);
        cudaFuncSetAttribute(k_depth_last,
                             cudaFuncAttributeMaxDynamicSharedMemorySize, sm);
        cudaFuncSetAttribute(k_depth_last,
                             cudaFuncAttributePreferredSharedMemoryCarveout, 100);
        k_depth_last<<<dim3(64, BB), 256, sm>>>(
            Wmsd, bias, convW, convB, sout_w, sout_b, out);
    }
}

// round 17
// speedup vs baseline: 1.3226x; 1.0399x over previous
#include <cuda_runtime.h>
#include <cstdint>

#define HH 512
#define WW 512
#define BB 4
#define NCH 31          // IN_C + DEPTH
#define HW (HH * WW)

// Scratch: feats tensor [B][31][H][W]  (130 MB device global; written before read)
__device__ float g_feats[(size_t)BB * NCH * HW];

// ---------------------------------------------------------------------------
// Init: feats[:,0] = x * sin_w + sin_b   (float4 vectorized)
// ---------------------------------------------------------------------------
__global__ void k_init(const float* __restrict__ x,
                       const float* __restrict__ sin_w,
                       const float* __restrict__ sin_b) {
    int idx = blockIdx.x * blockDim.x + threadIdx.x;   // 0 .. BB*HW/4-1
    float w = sin_w[0], b = sin_b[0];
    int bb = idx >> 16;            // HW/4 = 65536
    int p  = idx & 65535;
    float4 v = reinterpret_cast<const float4*>(x)[idx];
    float4 r = make_float4(fmaf(v.x, w, b), fmaf(v.y, w, b),
                           fmaf(v.z, w, b), fmaf(v.w, w, b));
    reinterpret_cast<float4*>(g_feats)[(size_t)(bb * NCH) * (HW / 4) + p] = r;
}

// ---------------------------------------------------------------------------
// Depth kernel (depths 0..28): TW=96 + triple-buffer + HOISTED stage geometry.
// Chunk geometry (global offset, zfill size) is channel-invariant: computed
// ONCE per thread into registers; each per-channel stage is then just
// {add plane base, add buffer base, cp.async}. Buffers padded to CHUNKS*1024
// floats so smem offset is the closed form tid*16 + j*4096 (out-of-range
// chunks zfill into padding).
// ---------------------------------------------------------------------------
template<int D>
__global__ void __launch_bounds__(256, 2)
k_depth(const float* __restrict__ Wmsd,
        const float* __restrict__ bias,
        int di) {
    constexpr int TILE   = 64;
    constexpr int RPT    = 16;               // output rows per thread
    constexpr int TW     = 96;               // staged window width (floats)
    constexpr int TH     = TILE + 2 * D;     // staged window height
    constexpr int NV4    = TH * (TW / 4);    // real float4 chunks per tile
    constexpr int CHUNKS = (NV4 + 255) / 256;
    constexpr int SBUFP  = CHUNKS * 1024;    // padded buffer size (floats)

    extern __shared__ float sbuf[];          // 3 buffers of SBUFP floats

    const int nin = di + 1;                  // input channels this depth
    const int tid = threadIdx.x;
    const int lx  = tid & 63;                // tile-local x (column)
    const int grp = tid >> 6;                // 0..3 -> row group
    const int bx  = blockIdx.x & 7;
    const int by  = blockIdx.x >> 3;
    const int b   = blockIdx.y;
    const int x0  = bx * TILE, y0 = by * TILE;

    const float* fbase = g_feats + (size_t)b * NCH * HW;
    const int oy0 = grp * RPT;
    const int sx  = lx + 16;                 // smem x of this thread's column

    // ---- Hoisted per-thread chunk geometry (channel-invariant) ----
    int gofs[CHUNKS];
    int gsz [CHUNKS];
#pragma unroll
    for (int j = 0; j < CHUNKS; j++) {
        int idx = tid + j * 256;
        int sy_ = idx / (TW / 4);
        int c4  = idx - sy_ * (TW / 4);
        int gy  = y0 - D + sy_;
        int gx  = x0 - 16 + c4 * 4;
        bool ok = (idx < NV4) && ((unsigned)gy < HH) && ((unsigned)gx < WW);
        gofs[j] = ok ? (gy * WW + gx) : 0;
        gsz [j] = ok ? 16 : 0;
    }
    const unsigned sbase = (unsigned)__cvta_generic_to_shared(sbuf) + tid * 16u;

    float acc[RPT];
    float bi = __ldg(bias + di);
#pragma unroll
    for (int k = 0; k < RPT; k++) acc[k] = bi;

    auto stage = [&](int c, int sel) {
        const float* plane = fbase + (size_t)c * HW;
        unsigned dsel = sbase + (unsigned)(sel * SBUFP) * 4u;
#pragma unroll
        for (int j = 0; j < CHUNKS; j++) {
            asm volatile("cp.async.cg.shared.global [%0], [%1], 16, %2;\n"
                         :: "r"(dsel + j * 4096u), "l"(plane + gofs[j]),
                            "r"(gsz[j]));
        }
        asm volatile("cp.async.commit_group;\n" ::: "memory");
    };

    // Prologue: stage channels 0 and 1
    stage(0, 0);
    if (nin > 1) stage(1, 1);

    int cur = 0;   // = c % 3
    for (int c = 0; c < nin; c++) {
        // Weight loads first — LDG latency overlaps the wait below.
        const float* wp = Wmsd + ((size_t)di * 30 + c) * 9;
        float w0 = __ldg(wp + 0), w1 = __ldg(wp + 1), w2 = __ldg(wp + 2);
        float w3 = __ldg(wp + 3), w4 = __ldg(wp + 4), w5 = __ldg(wp + 5);
        float w6 = __ldg(wp + 6), w7 = __ldg(wp + 7), w8 = __ldg(wp + 8);

        // Ensure stage(c) has landed. At most stage(c+1) may remain in flight.
        if (c + 1 < nin)
            asm volatile("cp.async.wait_group 1;\n" ::: "memory");
        else
            asm volatile("cp.async.wait_group 0;\n" ::: "memory");
        __syncthreads();

        // Stage c+2 into buffer (c+2)%3 — last read by compute(c-1), retired
        // by the barrier above. Lands during compute(c)+compute(c+1).
        if (c + 2 < nin) {
            int sel2 = cur + 2; if (sel2 >= 3) sel2 -= 3;
            stage(c + 2, sel2);
        }

        const float* sb_ = sbuf + cur * SBUFP;
#pragma unroll
        for (int rr = 0; rr < RPT + 2 * D; rr++) {
            const float* rp = sb_ + (oy0 + rr) * TW + sx;
            float v0 = rp[-D], v1 = rp[0], v2 = rp[D];
            // input row rr-D feeds out rows rr (w-row0), rr-D (w-row1),
            // rr-2D (w-row2)
            if (rr < RPT)
                acc[rr]       = fmaf(w0, v0, fmaf(w1, v1, fmaf(w2, v2, acc[rr])));
            if (rr >= D && rr < RPT + D)
                acc[rr - D]   = fmaf(w3, v0, fmaf(w4, v1, fmaf(w5, v2, acc[rr - D])));
            if (rr >= 2 * D)
                acc[rr - 2*D] = fmaf(w6, v0, fmaf(w7, v1, fmaf(w8, v2, acc[rr - 2*D])));
        }

        cur++; if (cur >= 3) cur = 0;
    }

    // ReLU + store new channel (index nin = di+1)
    float* op = g_feats + (size_t)b * NCH * HW + (size_t)nin * HW
              + (size_t)(y0 + oy0) * WW + (x0 + lx);
#pragma unroll
    for (int k = 0; k < RPT; k++)
        op[(size_t)k * WW] = fmaxf(acc[k], 0.0f);
}

// ---------------------------------------------------------------------------
// LAST depth kernel (depth 29, D=10, nin=30), same hoisted staging, with the
// final 1x1 conv fused (reuses the loaded center tap v1):
//   y = (yacc + convW[30]*relu(h29) + convB) * sout_w + sout_b -> d_out.
// ---------------------------------------------------------------------------
__global__ void __launch_bounds__(256, 2)
k_depth_last(const float* __restrict__ Wmsd,
             const float* __restrict__ bias,
             const float* __restrict__ convW,
             const float* __restrict__ convB,
             const float* __restrict__ sout_w,
             const float* __restrict__ sout_b,
             float* __restrict__ out) {
    constexpr int D      = 10;
    constexpr int DI     = 29;
    constexpr int TILE   = 64;
    constexpr int RPT    = 16;
    constexpr int TW     = 96;
    constexpr int TH     = TILE + 2 * D;
    constexpr int NV4    = TH * (TW / 4);
    constexpr int CHUNKS = (NV4 + 255) / 256;
    constexpr int SBUFP  = CHUNKS * 1024;

    extern __shared__ float sbuf[];          // 3 buffers

    const int nin = DI + 1;                  // 30
    const int tid = threadIdx.x;
    const int lx  = tid & 63;
    const int grp = tid >> 6;
    const int bx  = blockIdx.x & 7;
    const int by  = blockIdx.x >> 3;
    const int b   = blockIdx.y;
    const int x0  = bx * TILE, y0 = by * TILE;

    const float* fbase = g_feats + (size_t)b * NCH * HW;
    const int oy0 = grp * RPT;
    const int sx  = lx + 16;

    int gofs[CHUNKS];
    int gsz [CHUNKS];
#pragma unroll
    for (int j = 0; j < CHUNKS; j++) {
        int idx = tid + j * 256;
        int sy_ = idx / (TW / 4);
        int c4  = idx - sy_ * (TW / 4);
        int gy  = y0 - D + sy_;
        int gx  = x0 - 16 + c4 * 4;
        bool ok = (idx < NV4) && ((unsigned)gy < HH) && ((unsigned)gx < WW);
        gofs[j] = ok ? (gy * WW + gx) : 0;
        gsz [j] = ok ? 16 : 0;
    }
    const unsigned sbase = (unsigned)__cvta_generic_to_shared(sbuf) + tid * 16u;

    float acc[RPT];
    float yacc[RPT];
    {
        float bi = __ldg(bias + DI);
        float cb = convB[0];
#pragma unroll
        for (int k = 0; k < RPT; k++) { acc[k] = bi; yacc[k] = cb; }
    }

    auto stage = [&](int c, int sel) {
        const float* plane = fbase + (size_t)c * HW;
        unsigned dsel = sbase + (unsigned)(sel * SBUFP) * 4u;
#pragma unroll
        for (int j = 0; j < CHUNKS; j++) {
            asm volatile("cp.async.cg.shared.global [%0], [%1], 16, %2;\n"
                         :: "r"(dsel + j * 4096u), "l"(plane + gofs[j]),
                            "r"(gsz[j]));
        }
        asm volatile("cp.async.commit_group;\n" ::: "memory");
    };

    stage(0, 0);
    stage(1, 1);

    int cur = 0;
    for (int c = 0; c < nin; c++) {
        const float* wp = Wmsd + ((size_t)DI * 30 + c) * 9;
        float w0 = __ldg(wp + 0), w1 = __ldg(wp + 1), w2 = __ldg(wp + 2);
        float w3 = __ldg(wp + 3), w4 = __ldg(wp + 4), w5 = __ldg(wp + 5);
        float w6 = __ldg(wp + 6), w7 = __ldg(wp + 7), w8 = __ldg(wp + 8);
        float wF = __ldg(convW + c);

        if (c + 1 < nin)
            asm volatile("cp.async.wait_group 1;\n" ::: "memory");
        else
            asm volatile("cp.async.wait_group 0;\n" ::: "memory");
        __syncthreads();

        if (c + 2 < nin) {
            int sel2 = cur + 2; if (sel2 >= 3) sel2 -= 3;
            stage(c + 2, sel2);
        }

        const float* sb_ = sbuf + cur * SBUFP;
#pragma unroll
        for (int rr = 0; rr < RPT + 2 * D; rr++) {
            const float* rp = sb_ + (oy0 + rr) * TW + sx;
            float v0 = rp[-D], v1 = rp[0], v2 = rp[D];
            if (rr < RPT)
                acc[rr]       = fmaf(w0, v0, fmaf(w1, v1, fmaf(w2, v2, acc[rr])));
            if (rr >= D && rr < RPT + D) {
                acc[rr - D]   = fmaf(w3, v0, fmaf(w4, v1, fmaf(w5, v2, acc[rr - D])));
                // v1 IS feats_c at output pixel row (y0+oy0+rr-D): fold 1x1
                yacc[rr - D]  = fmaf(wF, v1, yacc[rr - D]);
            }
            if (rr >= 2 * D)
                acc[rr - 2*D] = fmaf(w6, v0, fmaf(w7, v1, fmaf(w8, v2, acc[rr - 2*D])));
        }

        cur++; if (cur >= 3) cur = 0;
    }

    // h29 = relu(acc); y = (yacc + convW[30]*h29)*sw + sb -> out
    float wL = __ldg(convW + 30);
    float sw = sout_w[0], sb = sout_b[0];
    float* op = out + (size_t)b * HW + (size_t)(y0 + oy0) * WW + (x0 + lx);
#pragma unroll
    for (int k = 0; k < RPT; k++) {
        float h = fmaxf(acc[k], 0.0f);
        float y = fmaf(wL, h, yacc[k]);
        op[(size_t)k * WW] = fmaf(y, sw, sb);
    }
}

// ---------------------------------------------------------------------------
// Launch
// ---------------------------------------------------------------------------
template<int D>
static inline void launch_depth(int i, const float* Wmsd, const float* bias) {
    constexpr int TH     = 64 + 2 * D;
    constexpr int CHUNKS = (TH * 24 + 255) / 256;
    int sm = 3 * CHUNKS * 1024 * (int)sizeof(float);
    cudaFuncSetAttribute(k_depth<D>, cudaFuncAttributeMaxDynamicSharedMemorySize, sm);
    cudaFuncSetAttribute(k_depth<D>,
                         cudaFuncAttributePreferredSharedMemoryCarveout, 100);
    k_depth<D><<<dim3(64, BB), 256, sm>>>(Wmsd, bias, i);
}

extern "C" void kernel_launch(void* const* d_in, const int* in_sizes, int n_in,
                              void* d_out, int out_size) {
    const float* x      = (const float*)d_in[0];
    const float* Wmsd   = (const float*)d_in[1];
    const float* bias   = (const float*)d_in[2];
    const float* convW  = (const float*)d_in[3];
    const float* convB  = (const float*)d_in[4];
    const float* sin_w  = (const float*)d_in[5];
    const float* sin_b  = (const float*)d_in[6];
    const float* sout_w = (const float*)d_in[7];
    const float* sout_b = (const float*)d_in[8];
    float* out = (float*)d_out;

    k_init<<<(BB * HW / 4) / 256, 256>>>(x, sin_w, sin_b);

    for (int i = 0; i < 29; i++) {
        int d = (i % 10) + 1;
        switch (d) {
            case  1: launch_depth< 1>(i, Wmsd, bias); break;
            case  2: launch_depth< 2>(i, Wmsd, bias); break;
            case  3: launch_depth< 3>(i, Wmsd, bias); break;
            case  4: launch_depth< 4>(i, Wmsd, bias); break;
            case  5: launch_depth< 5>(i, Wmsd, bias); break;
            case  6: launch_depth< 6>(i, Wmsd, bias); break;
            case  7: launch_depth< 7>(i, Wmsd, bias); break;
            case  8: launch_depth< 8>(i, Wmsd, bias); break;
            case  9: launch_depth< 9>(i, Wmsd, bias); break;
            default: launch_depth<10>(i, Wmsd, bias); break;
        }
    }

    // Depth 29 (D=10) with fused final 1x1 conv + affine; writes d_out.
    {
        constexpr int CHUNKS_L = ((64 + 20) * 24 + 255) / 256;
        int sm = 3 * CHUNKS_L * 1024 * (int)sizeof(float);
        cudaFuncSetAttribute(k_depth_last,
                             cudaFuncAttributeMaxDynamicSharedMemorySize, sm);
        cudaFuncSetAttribute(k_depth_last,
                             cudaFuncAttributePreferredSharedMemoryCarveout, 100);
        k_depth_last<<<dim3(64, BB), 256, sm>>>(
            Wmsd, bias, convW, convB, sout_w, sout_b, out);
    }
}